// round 1
// baseline (speedup 1.0000x reference)
#include <cuda_runtime.h>
#include <cstdint>

#define OUT_F 4096
#define IN_F  4096
#define M_TOT 8192

#define BM 128
#define BN 128
#define BK 16
#define SSTR 20           // padded smem row stride (floats): conflict-free for frag loads
#define NK (IN_F / BK)    // 256 k-iterations

// Dequantized weights, tf32-rounded, row-major [OUT_F][IN_F]. 64 MB device global scratch.
__device__ float g_W[OUT_F * IN_F];

__device__ __forceinline__ uint32_t f2tf32(float f) {
    uint32_t r;
    asm("cvt.rna.tf32.f32 %0, %1;" : "=r"(r) : "f"(f));
    return r;
}

// ---------------------------------------------------------------------------
// Dequant: each int32 carries one byte = two 4-bit codes -> two fp32 weights.
// flat index f = 2*i (low nibble), 2*i+1 (high). group g = f/128 = i/64.
// ---------------------------------------------------------------------------
__global__ void dequant_kernel(const int* __restrict__ packed,
                               const float* __restrict__ scales,
                               const float* __restrict__ offsets) {
    int i = blockIdx.x * blockDim.x + threadIdx.x;   // exactly OUT_F*IN_F/2 threads
    int p = packed[i];
    int g = i >> 6;
    float s = scales[g];
    float o = offsets[g];
    float w0 = (float)(p & 0xF) * s + o;
    float w1 = (float)((p >> 4) & 0xF) * s + o;
    float2 out;
    out.x = __uint_as_float(f2tf32(w0));
    out.y = __uint_as_float(f2tf32(w1));
    *reinterpret_cast<float2*>(&g_W[2 * i]) = out;
}

// ---------------------------------------------------------------------------
// GEMM: Y[m][n] = sum_k X[m][k] * W[n][k] + bias[n]
// CTA tile 128x128, BK=16, 256 threads (8 warps, each 64x32 via m16n8k8 tf32).
// Double-buffered smem, global loads staged through registers (X gets tf32
// rounding applied during the smem store; W is pre-rounded by dequant).
// ---------------------------------------------------------------------------
__global__ void __launch_bounds__(256, 2)
gemm_kernel(const float* __restrict__ X,
            const float* __restrict__ bias,
            float* __restrict__ Y) {
    __shared__ float As[2][BM * SSTR];
    __shared__ float Bs[2][BN * SSTR];

    const int tid  = threadIdx.x;
    const int warp = tid >> 5;
    const int lane = tid & 31;
    const int gid  = lane >> 2;   // group id (row within fragment)
    const int tig  = lane & 3;    // thread-in-group (col within fragment)

    const int wm = (warp >> 2) * 64;  // warp m-offset within CTA tile (0 or 64)
    const int wn = (warp & 3) * 32;   // warp n-offset within CTA tile

    const int m0 = blockIdx.y * BM;
    const int n0 = blockIdx.x * BN;

    // global->smem staging indices: 512 float4 per 128x16 tile, 2 per thread
    const int id0 = tid;
    const int id1 = tid + 256;
    const int ar0 = id0 >> 2, ac0 = (id0 & 3) << 2;
    const int ar1 = id1 >> 2, ac1 = (id1 & 3) << 2;

    const float* Ab = X   + (size_t)m0 * IN_F;
    const float* Bb = g_W + (size_t)n0 * IN_F;

    float c[4][4][4];
#pragma unroll
    for (int i = 0; i < 4; i++)
#pragma unroll
        for (int j = 0; j < 4; j++)
#pragma unroll
            for (int r = 0; r < 4; r++) c[i][j][r] = 0.0f;

    // ---- prologue: load tile 0 into buffer 0 ----
    {
        float4 a0 = *(const float4*)(Ab + ar0 * IN_F + ac0);
        float4 a1 = *(const float4*)(Ab + ar1 * IN_F + ac1);
        float4 b0 = *(const float4*)(Bb + ar0 * IN_F + ac0);
        float4 b1 = *(const float4*)(Bb + ar1 * IN_F + ac1);
        float4 t;
        t.x = __uint_as_float(f2tf32(a0.x)); t.y = __uint_as_float(f2tf32(a0.y));
        t.z = __uint_as_float(f2tf32(a0.z)); t.w = __uint_as_float(f2tf32(a0.w));
        *(float4*)&As[0][ar0 * SSTR + ac0] = t;
        t.x = __uint_as_float(f2tf32(a1.x)); t.y = __uint_as_float(f2tf32(a1.y));
        t.z = __uint_as_float(f2tf32(a1.z)); t.w = __uint_as_float(f2tf32(a1.w));
        *(float4*)&As[0][ar1 * SSTR + ac1] = t;
        *(float4*)&Bs[0][ar0 * SSTR + ac0] = b0;
        *(float4*)&Bs[0][ar1 * SSTR + ac1] = b1;
    }
    __syncthreads();

    for (int kt = 0; kt < NK; kt++) {
        const int cur = kt & 1;
        const bool hasNext = (kt + 1 < NK);

        float4 sa0, sa1, sb0, sb1;
        if (hasNext) {
            const int ko = (kt + 1) * BK;
            sa0 = *(const float4*)(Ab + ar0 * IN_F + ko + ac0);
            sa1 = *(const float4*)(Ab + ar1 * IN_F + ko + ac1);
            sb0 = *(const float4*)(Bb + ar0 * IN_F + ko + ac0);
            sb1 = *(const float4*)(Bb + ar1 * IN_F + ko + ac1);
        }

        // ---- compute on buffer `cur` ----
        const float* Ac = As[cur];
        const float* Bc = Bs[cur];
#pragma unroll
        for (int kk = 0; kk < 2; kk++) {
            const int k0 = kk * 8;
            uint32_t a[4][4], b[4][2];
#pragma unroll
            for (int i = 0; i < 4; i++) {
                const int r = wm + i * 16 + gid;
                a[i][0] = __float_as_uint(Ac[r * SSTR + k0 + tig]);
                a[i][1] = __float_as_uint(Ac[(r + 8) * SSTR + k0 + tig]);
                a[i][2] = __float_as_uint(Ac[r * SSTR + k0 + tig + 4]);
                a[i][3] = __float_as_uint(Ac[(r + 8) * SSTR + k0 + tig + 4]);
            }
#pragma unroll
            for (int j = 0; j < 4; j++) {
                const int rn = wn + j * 8 + gid;
                b[j][0] = __float_as_uint(Bc[rn * SSTR + k0 + tig]);
                b[j][1] = __float_as_uint(Bc[rn * SSTR + k0 + tig + 4]);
            }
#pragma unroll
            for (int i = 0; i < 4; i++)
#pragma unroll
                for (int j = 0; j < 4; j++) {
                    asm volatile(
                        "mma.sync.aligned.m16n8k8.row.col.f32.tf32.tf32.f32 "
                        "{%0,%1,%2,%3}, {%4,%5,%6,%7}, {%8,%9}, {%0,%1,%2,%3};\n"
                        : "+f"(c[i][j][0]), "+f"(c[i][j][1]),
                          "+f"(c[i][j][2]), "+f"(c[i][j][3])
                        : "r"(a[i][0]), "r"(a[i][1]), "r"(a[i][2]), "r"(a[i][3]),
                          "r"(b[j][0]), "r"(b[j][1]));
                }
        }

        if (hasNext) {
            const int nb = cur ^ 1;
            float4 t;
            t.x = __uint_as_float(f2tf32(sa0.x)); t.y = __uint_as_float(f2tf32(sa0.y));
            t.z = __uint_as_float(f2tf32(sa0.z)); t.w = __uint_as_float(f2tf32(sa0.w));
            *(float4*)&As[nb][ar0 * SSTR + ac0] = t;
            t.x = __uint_as_float(f2tf32(sa1.x)); t.y = __uint_as_float(f2tf32(sa1.y));
            t.z = __uint_as_float(f2tf32(sa1.z)); t.w = __uint_as_float(f2tf32(sa1.w));
            *(float4*)&As[nb][ar1 * SSTR + ac1] = t;
            *(float4*)&Bs[nb][ar0 * SSTR + ac0] = sb0;
            *(float4*)&Bs[nb][ar1 * SSTR + ac1] = sb1;
        }
        __syncthreads();
    }

    // ---- epilogue: bias + store (float2, coalesced in pairs) ----
#pragma unroll
    for (int i = 0; i < 4; i++) {
        const int m = m0 + wm + i * 16 + gid;
#pragma unroll
        for (int j = 0; j < 4; j++) {
            const int n = n0 + wn + j * 8 + 2 * tig;
            const float b0 = bias[n];
            const float b1 = bias[n + 1];
            float2 v;
            v.x = c[i][j][0] + b0;
            v.y = c[i][j][1] + b1;
            *(float2*)&Y[(size_t)m * OUT_F + n] = v;
            v.x = c[i][j][2] + b0;
            v.y = c[i][j][3] + b1;
            *(float2*)&Y[(size_t)(m + 8) * OUT_F + n] = v;
        }
    }
}

extern "C" void kernel_launch(void* const* d_in, const int* in_sizes, int n_in,
                              void* d_out, int out_size) {
    const float* x       = (const float*)d_in[0];
    const int*   packed  = (const int*)d_in[1];
    const float* scales  = (const float*)d_in[2];
    const float* offsets = (const float*)d_in[3];
    const float* bias    = (const float*)d_in[4];
    float* out = (float*)d_out;

    // 1) dequant packed 4-bit -> g_W (tf32-rounded fp32)
    const int n_packed = OUT_F * IN_F / 2;          // 8,388,608
    dequant_kernel<<<n_packed / 256, 256>>>(packed, scales, offsets);

    // 2) GEMM: [8192,4096] x [4096,4096]^T + bias
    dim3 grid(OUT_F / BN, M_TOT / BM);              // (32, 64)
    gemm_kernel<<<grid, 256>>>(x, bias, out);
}

// round 3
// speedup vs baseline: 3.4011x; 3.4011x over previous
#include <cuda_runtime.h>
#include <cstdint>

#define OUT_F 4096
#define IN_F  4096
#define M_TOT 8192

#define BM 256
#define BN 256
#define KC 32                    // K floats per stage (128 bytes per row)
#define NKI (IN_F / KC)          // 128 k-iterations
#define STAGES 3
#define STAGE_BYTES 65536        // A 32KB (256 rows x 128B) + B 32KB
#define SMEM_STAGE0 1024
#define SMEM_TOTAL (SMEM_STAGE0 + STAGES * STAGE_BYTES)   // 197632

// idesc: dtype=F32(1<<4), atype=TF32(2<<7), btype=TF32(2<<10), N/8<<17, M/16<<24
#define MMA_IDESC ((1u<<4) | (2u<<7) | (2u<<10) | ((BN/8u)<<17) | ((128u/16u)<<24))

// SW128 K-major smem descriptor base: layout=2, version=1, SBO=64, LBO=1
#define DESC_BASE ((2ull<<61) | (1ull<<46) | (64ull<<32) | (1ull<<16))
#define MAKE_DESC(a) (DESC_BASE | ((uint64_t)((a) >> 4) & 0x3FFF))

__device__ float g_W[(size_t)OUT_F * IN_F];   // dequantized, tf32-RNA-rounded
__device__ float g_X[(size_t)M_TOT * IN_F];   // x, tf32-RNA-rounded

// ---------------------------------------------------------------- helpers
__device__ __forceinline__ uint32_t f2tf32(float f) {
    uint32_t r;
    asm("cvt.rna.tf32.f32 %0, %1;" : "=r"(r) : "f"(f));
    return r;
}
__device__ __forceinline__ uint32_t smem_u32(const void* p) {
    uint32_t a;
    asm("{ .reg .u64 t; cvta.to.shared.u64 t, %1; cvt.u32.u64 %0, t; }" : "=r"(a) : "l"(p));
    return a;
}
#define CP_ASYNC16(dst, src) \
    asm volatile("cp.async.cg.shared.global [%0], [%1], 16;" :: "r"(dst), "l"(src) : "memory")
#define CP_COMMIT() asm volatile("cp.async.commit_group;" ::: "memory")
#define CP_WAIT(n)  asm volatile("cp.async.wait_group %0;" :: "n"(n) : "memory")

#define MBARRIER_INIT(a, c) \
    asm volatile("mbarrier.init.shared.b64 [%0], %1;" :: "r"(a), "r"(c) : "memory")
#define MBARRIER_INVAL(a) \
    asm volatile("mbarrier.inval.shared.b64 [%0];" :: "r"(a) : "memory")
#define MBARRIER_WAIT_PARITY(addr, par) do {                                   \
    uint32_t _m = (addr); uint32_t _p = (par); uint32_t _d;                    \
    asm volatile("{\n\t.reg .pred p;\n\t"                                      \
        "mbarrier.try_wait.parity.acquire.cta.shared::cta.b64 p, [%1], %2;\n\t"\
        "selp.b32 %0, 1, 0, p;\n\t}"                                           \
        : "=r"(_d) : "r"(_m), "r"(_p) : "memory");                             \
    if (!_d) {                                                                  \
        asm volatile("{\n\t.reg .pred P1;\n\t"                                 \
            "WL_%=:\n\t"                                                       \
            "mbarrier.try_wait.parity.acquire.cta.shared::cta.b64 P1, [%0], %1, 0x989680;\n\t" \
            "@P1 bra.uni WD_%=;\n\t"                                           \
            "bra.uni WL_%=;\n\t"                                               \
            "WD_%=:\n\t}"                                                      \
            :: "r"(_m), "r"(_p) : "memory");                                   \
    }                                                                           \
} while (0)

// ---------------------------------------------------------------- prepasses
__global__ void dequant_kernel(const int* __restrict__ packed,
                               const float* __restrict__ scales,
                               const float* __restrict__ offsets) {
    int i = blockIdx.x * blockDim.x + threadIdx.x;   // OUT_F*IN_F/2 threads
    int p = packed[i];
    int g = i >> 6;
    float s = scales[g];
    float o = offsets[g];
    float2 out;
    out.x = __uint_as_float(f2tf32((float)(p & 0xF) * s + o));
    out.y = __uint_as_float(f2tf32((float)((p >> 4) & 0xF) * s + o));
    *reinterpret_cast<float2*>(&g_W[2 * (size_t)i]) = out;
}

__global__ void xround_kernel(const float* __restrict__ x) {
    size_t i = (size_t)blockIdx.x * blockDim.x + threadIdx.x;  // M_TOT*IN_F/4 threads
    float4 v = reinterpret_cast<const float4*>(x)[i];
    float4 o;
    o.x = __uint_as_float(f2tf32(v.x));
    o.y = __uint_as_float(f2tf32(v.y));
    o.z = __uint_as_float(f2tf32(v.z));
    o.w = __uint_as_float(f2tf32(v.w));
    reinterpret_cast<float4*>(g_X)[i] = o;
}

// ---------------------------------------------------------------- main GEMM
// Everything tcgen05-specific lives behind __CUDA_ARCH_FEAT_SM103_ALL so the
// harness's compute_103 (non-'a') PTX fallback pass compiles an empty body.
// The GB300 runs the sm_103a cubin, where the full kernel exists.

#if defined(__CUDA_ARCH_FEAT_SM103_ALL)
#define HAS_TCGEN05 1
#else
#define HAS_TCGEN05 0
#endif

#if HAS_TCGEN05
#define TCGEN05_ALLOC(sa, n) \
    asm volatile("tcgen05.alloc.cta_group::1.sync.aligned.shared::cta.b32 [%0], %1;" \
                 :: "r"(sa), "r"((uint32_t)(n)) : "memory")
#define TCGEN05_DEALLOC(t, n) \
    asm volatile("tcgen05.dealloc.cta_group::1.sync.aligned.b32 %0, %1;" :: "r"(t), "r"((uint32_t)(n)))
#define TCGEN05_RELINQUISH() \
    asm volatile("tcgen05.relinquish_alloc_permit.cta_group::1.sync.aligned;")
#define TCGEN05_COMMIT(mb) \
    asm volatile("tcgen05.commit.cta_group::1.mbarrier::arrive::one.shared::cluster.b64 [%0];" \
                 :: "r"(mb) : "memory")
#define TCGEN05_FENCE_AFTER() asm volatile("tcgen05.fence::after_thread_sync;" ::: "memory")
#define TCGEN05_FENCE_BEFORE() asm volatile("tcgen05.fence::before_thread_sync;" ::: "memory")
#define TCGEN05_WAIT_LD() asm volatile("tcgen05.wait::ld.sync.aligned;" ::: "memory")
#define FENCE_PROXY_ASYNC() asm volatile("fence.proxy.async.shared::cta;" ::: "memory")

#define LDTM_X32(r, a) \
    asm volatile("tcgen05.ld.sync.aligned.32x32b.x32.b32 "                     \
        "{%0,%1,%2,%3,%4,%5,%6,%7,%8,%9,%10,%11,%12,%13,%14,%15,"              \
        "%16,%17,%18,%19,%20,%21,%22,%23,%24,%25,%26,%27,%28,%29,%30,%31}, [%32];" \
        : "=r"((r)[0]), "=r"((r)[1]), "=r"((r)[2]), "=r"((r)[3]),              \
          "=r"((r)[4]), "=r"((r)[5]), "=r"((r)[6]), "=r"((r)[7]),              \
          "=r"((r)[8]), "=r"((r)[9]), "=r"((r)[10]), "=r"((r)[11]),            \
          "=r"((r)[12]), "=r"((r)[13]), "=r"((r)[14]), "=r"((r)[15]),          \
          "=r"((r)[16]), "=r"((r)[17]), "=r"((r)[18]), "=r"((r)[19]),          \
          "=r"((r)[20]), "=r"((r)[21]), "=r"((r)[22]), "=r"((r)[23]),          \
          "=r"((r)[24]), "=r"((r)[25]), "=r"((r)[26]), "=r"((r)[27]),          \
          "=r"((r)[28]), "=r"((r)[29]), "=r"((r)[30]), "=r"((r)[31])           \
        : "r"(a))

__device__ __forceinline__ void mma_tf32_ss(uint32_t d, uint64_t ad, uint64_t bd,
                                            uint32_t idesc, uint32_t en) {
    asm volatile(
        "{\n\t.reg .pred p;\n\tsetp.ne.u32 p, %5, 0;\n\t"
        "tcgen05.mma.cta_group::1.kind::tf32 [%0], %1, %2, %3, {%4,%4,%4,%4}, p;\n\t}"
        :: "r"(d), "l"(ad), "l"(bd), "r"(idesc), "r"(0u), "r"(en) : "memory");
}

__device__ __forceinline__ void load_stage(uint32_t sb, int buf, int kt,
                                           int m0, int n0, int tid) {
    const uint32_t abase = sb + SMEM_STAGE0 + buf * STAGE_BYTES;
    const uint32_t bbase = abase + 32768;
    const float* Xp = g_X + (size_t)m0 * IN_F + (size_t)kt * KC;
    const float* Wp = g_W + (size_t)n0 * IN_F + (size_t)kt * KC;
#pragma unroll
    for (int i = 0; i < 8; i++) {                    // A: 256 rows x 8 chunks
        int id = i * 256 + tid;
        int row = id >> 3, c = id & 7;
        uint32_t sw = (uint32_t)(row * 128 + ((c ^ (row & 7)) << 4));
        CP_ASYNC16(abase + sw, __cvta_generic_to_global(Xp + (size_t)row * IN_F + c * 4));
    }
#pragma unroll
    for (int i = 0; i < 8; i++) {                    // B: 256 rows x 8 chunks
        int id = i * 256 + tid;
        int row = id >> 3, c = id & 7;
        uint32_t sw = (uint32_t)(row * 128 + ((c ^ (row & 7)) << 4));
        CP_ASYNC16(bbase + sw, __cvta_generic_to_global(Wp + (size_t)row * IN_F + c * 4));
    }
}
#endif  // HAS_TCGEN05

__global__ void __launch_bounds__(256, 1)
gemm_tc(const float* __restrict__ bias, float* __restrict__ Y) {
#if HAS_TCGEN05
    extern __shared__ char smem[];
    const uint32_t sb = smem_u32(smem);
    const int tid = threadIdx.x;
    const int wid = tid >> 5;
    const int lane = tid & 31;
    const int m0 = blockIdx.y * BM;
    const int n0 = blockIdx.x * BN;

    if (wid == 0) TCGEN05_ALLOC(sb, 512);
    if (tid == 0) {
#pragma unroll
        for (int s = 0; s < STAGES; s++) MBARRIER_INIT(sb + 8 + s * 8, 1);
    }
    __syncthreads();
    uint32_t tmem;
    asm volatile("ld.shared.b32 %0, [%1];" : "=r"(tmem) : "r"(sb));

    // prologue: fill all 3 stages
#pragma unroll
    for (int p = 0; p < STAGES; p++) {
        load_stage(sb, p, p, m0, n0, tid);
        CP_COMMIT();
    }

    for (int kt = 0; kt < NKI; kt++) {
        // stage kt's cp.async group complete
        if (kt < NKI - 2)      { CP_WAIT(2); }
        else if (kt == NKI - 2){ CP_WAIT(1); }
        else                   { CP_WAIT(0); }
        FENCE_PROXY_ASYNC();
        __syncthreads();

        if (tid == 0) {
            const uint32_t ss = sb + SMEM_STAGE0 + (kt % STAGES) * STAGE_BYTES;
            const uint64_t a0 = MAKE_DESC(ss);
            const uint64_t a1 = MAKE_DESC(ss + 32768/2);   // A half 1: +16KB = +1024 units
            const uint64_t bd = MAKE_DESC(ss + 32768);
#pragma unroll
            for (int ks = 0; ks < 4; ks++) {               // 4 x K=8 within 128B row
                uint32_t en = (kt > 0 || ks > 0) ? 1u : 0u;
                mma_tf32_ss(tmem,       a0 + ks * 2, bd + ks * 2, MMA_IDESC, en);
                mma_tf32_ss(tmem + 256, a1 + ks * 2, bd + ks * 2, MMA_IDESC, en);
            }
            TCGEN05_COMMIT(sb + 8 + (kt % STAGES) * 8);
        }

        const int nk = kt + STAGES;
        if (nk < NKI) {
            // buffer kt%STAGES is being consumed by the MMAs just committed:
            // wait for that commit before overwriting
            MBARRIER_WAIT_PARITY(sb + 8 + (kt % STAGES) * 8, (uint32_t)((kt / STAGES) & 1));
            load_stage(sb, kt % STAGES, nk, m0, n0, tid);
            CP_COMMIT();
        }
    }

    // wait for final commit (last mma of kt=NKI-1; queue is in-order)
    {
        const int lk = NKI - 1;
        MBARRIER_WAIT_PARITY(sb + 8 + (lk % STAGES) * 8, (uint32_t)((lk / STAGES) & 1));
    }
    TCGEN05_FENCE_AFTER();

    // epilogue: warps 0-3 read TMEM (lane l of warp w = M row w*32+l), add bias, store
    if (wid < 4) {
#pragma unroll
        for (int half = 0; half < 2; half++) {
            const int m = m0 + half * 128 + wid * 32 + lane;
            float* yrow = Y + (size_t)m * OUT_F + n0;
#pragma unroll
            for (int c0 = 0; c0 < 256; c0 += 32) {
                uint32_t r[32];
                LDTM_X32(r, tmem + half * 256 + c0);
                TCGEN05_WAIT_LD();
                const float* bp = bias + n0 + c0;
#pragma unroll
                for (int j = 0; j < 32; j += 4) {
                    float4 v;
                    v.x = __uint_as_float(r[j + 0]) + bp[j + 0];
                    v.y = __uint_as_float(r[j + 1]) + bp[j + 1];
                    v.z = __uint_as_float(r[j + 2]) + bp[j + 2];
                    v.w = __uint_as_float(r[j + 3]) + bp[j + 3];
                    *reinterpret_cast<float4*>(yrow + c0 + j) = v;
                }
            }
        }
        TCGEN05_FENCE_BEFORE();
    }

    __syncthreads();
    if (tid == 0) {
#pragma unroll
        for (int s = 0; s < STAGES; s++) MBARRIER_INVAL(sb + 8 + s * 8);
    }
    __syncthreads();
    if (wid == 0) {
        TCGEN05_RELINQUISH();
        TCGEN05_DEALLOC(tmem, 512);
    }
#endif  // HAS_TCGEN05
}

// ---------------------------------------------------------------- launch
extern "C" void kernel_launch(void* const* d_in, const int* in_sizes, int n_in,
                              void* d_out, int out_size) {
    const float* x       = (const float*)d_in[0];
    const int*   packed  = (const int*)d_in[1];
    const float* scales  = (const float*)d_in[2];
    const float* offsets = (const float*)d_in[3];
    const float* bias    = (const float*)d_in[4];
    float* out = (float*)d_out;

    // prepass 1: x -> g_X (tf32 RNA)
    xround_kernel<<<(M_TOT * (IN_F / 4)) / 256, 256>>>(x);
    // prepass 2: dequant 4-bit -> g_W (tf32 RNA)
    dequant_kernel<<<(OUT_F * IN_F / 2) / 256, 256>>>(packed, scales, offsets);

    // main GEMM: 256x256 CTA tiles, tcgen05 tf32
    static bool attr_set = false;
    if (!attr_set) {
        cudaFuncSetAttribute(gemm_tc, cudaFuncAttributeMaxDynamicSharedMemorySize, SMEM_TOTAL);
        attr_set = true;
    }
    dim3 grid(OUT_F / BN, M_TOT / BM);   // (16, 32)
    gemm_tc<<<grid, 256, SMEM_TOTAL>>>(bias, out);
}

// round 4
// speedup vs baseline: 4.7218x; 1.3883x over previous
#include <cuda_runtime.h>
#include <cstdint>

#define OUT_F 4096
#define IN_F  4096
#define M_TOT 8192

#define BM 256
#define BN 256
#define KC 32                    // K floats per stage (128 bytes per row)
#define NKI (IN_F / KC)          // 128 k-iterations
#define STAGES 3
#define STAGE_BYTES 65536        // A 32KB (256 rows x 128B) + B 32KB
#define SMEM_STAGE0 1024
#define SMEM_TOTAL (SMEM_STAGE0 + STAGES * STAGE_BYTES)   // 197632
#define NT 384                   // warps 0-7 producers, warp8 MMA, warps 8-11 epilogue

// idesc: dtype=F32(1<<4), atype=TF32(2<<7), btype=TF32(2<<10), N/8<<17, M/16<<24
#define MMA_IDESC ((1u<<4) | (2u<<7) | (2u<<10) | ((BN/8u)<<17) | ((128u/16u)<<24))

// SW128 K-major smem descriptor base: layout=2, version=1, SBO=64, LBO=1
#define DESC_BASE ((2ull<<61) | (1ull<<46) | (64ull<<32) | (1ull<<16))
#define MAKE_DESC(a) (DESC_BASE | ((uint64_t)((a) >> 4) & 0x3FFF))

__device__ float g_W[(size_t)OUT_F * IN_F];   // dequantized, tf32-RNA-rounded
__device__ float g_X[(size_t)M_TOT * IN_F];   // x, tf32-RNA-rounded

// ---------------------------------------------------------------- helpers
__device__ __forceinline__ uint32_t f2tf32(float f) {
    uint32_t r;
    asm("cvt.rna.tf32.f32 %0, %1;" : "=r"(r) : "f"(f));
    return r;
}
__device__ __forceinline__ uint32_t smem_u32(const void* p) {
    uint32_t a;
    asm("{ .reg .u64 t; cvta.to.shared.u64 t, %1; cvt.u32.u64 %0, t; }" : "=r"(a) : "l"(p));
    return a;
}
#define CP_ASYNC16(dst, src) \
    asm volatile("cp.async.cg.shared.global [%0], [%1], 16;" :: "r"(dst), "l"(src) : "memory")
#define CP_ASYNC_MBAR_ARRIVE(mb) \
    asm volatile("cp.async.mbarrier.arrive.noinc.shared.b64 [%0];" :: "r"(mb) : "memory")

#define MBARRIER_INIT(a, c) \
    asm volatile("mbarrier.init.shared.b64 [%0], %1;" :: "r"(a), "r"(c) : "memory")
#define MBARRIER_INVAL(a) \
    asm volatile("mbarrier.inval.shared.b64 [%0];" :: "r"(a) : "memory")
#define MBARRIER_WAIT_PARITY(addr, par) do {                                   \
    uint32_t _m = (addr); uint32_t _p = (par); uint32_t _d;                    \
    asm volatile("{\n\t.reg .pred p;\n\t"                                      \
        "mbarrier.try_wait.parity.acquire.cta.shared::cta.b64 p, [%1], %2;\n\t"\
        "selp.b32 %0, 1, 0, p;\n\t}"                                           \
        : "=r"(_d) : "r"(_m), "r"(_p) : "memory");                             \
    if (!_d) {                                                                  \
        asm volatile("{\n\t.reg .pred P1;\n\t"                                 \
            "WL_%=:\n\t"                                                       \
            "mbarrier.try_wait.parity.acquire.cta.shared::cta.b64 P1, [%0], %1, 0x989680;\n\t" \
            "@P1 bra.uni WD_%=;\n\t"                                           \
            "bra.uni WL_%=;\n\t"                                               \
            "WD_%=:\n\t}"                                                      \
            :: "r"(_m), "r"(_p) : "memory");                                   \
    }                                                                           \
} while (0)

// ---------------------------------------------------------------- prepass
// blocks [0, 32768): round X to tf32 (RNA) into g_X
// blocks [32768, 65536): dequant packed 4-bit -> g_W (tf32 RNA)
__global__ void prepass_kernel(const float* __restrict__ x,
                               const int* __restrict__ packed,
                               const float* __restrict__ scales,
                               const float* __restrict__ offsets) {
    if (blockIdx.x < 32768) {
        size_t i = (size_t)blockIdx.x * blockDim.x + threadIdx.x;  // float4 index
        float4 v = reinterpret_cast<const float4*>(x)[i];
        float4 o;
        o.x = __uint_as_float(f2tf32(v.x));
        o.y = __uint_as_float(f2tf32(v.y));
        o.z = __uint_as_float(f2tf32(v.z));
        o.w = __uint_as_float(f2tf32(v.w));
        reinterpret_cast<float4*>(g_X)[i] = o;
    } else {
        int i = (blockIdx.x - 32768) * blockDim.x + threadIdx.x;  // packed index
        int p = packed[i];
        int g = i >> 6;
        float s = scales[g];
        float o = offsets[g];
        float2 out;
        out.x = __uint_as_float(f2tf32((float)(p & 0xF) * s + o));
        out.y = __uint_as_float(f2tf32((float)((p >> 4) & 0xF) * s + o));
        *reinterpret_cast<float2*>(&g_W[2 * (size_t)i]) = out;
    }
}

// ---------------------------------------------------------------- main GEMM
// tcgen05 bits gated on sm_103a feature macro so the harness's plain
// compute_103 PTX fallback pass compiles an empty body (GB300 runs sm_103a cubin).
#if defined(__CUDA_ARCH_FEAT_SM103_ALL)
#define HAS_TCGEN05 1
#else
#define HAS_TCGEN05 0
#endif

#if HAS_TCGEN05
#define TCGEN05_ALLOC(sa, n) \
    asm volatile("tcgen05.alloc.cta_group::1.sync.aligned.shared::cta.b32 [%0], %1;" \
                 :: "r"(sa), "r"((uint32_t)(n)) : "memory")
#define TCGEN05_DEALLOC(t, n) \
    asm volatile("tcgen05.dealloc.cta_group::1.sync.aligned.b32 %0, %1;" :: "r"(t), "r"((uint32_t)(n)))
#define TCGEN05_RELINQUISH() \
    asm volatile("tcgen05.relinquish_alloc_permit.cta_group::1.sync.aligned;")
#define TCGEN05_COMMIT(mb) \
    asm volatile("tcgen05.commit.cta_group::1.mbarrier::arrive::one.shared::cluster.b64 [%0];" \
                 :: "r"(mb) : "memory")
#define TCGEN05_FENCE_AFTER() asm volatile("tcgen05.fence::after_thread_sync;" ::: "memory")
#define TCGEN05_FENCE_BEFORE() asm volatile("tcgen05.fence::before_thread_sync;" ::: "memory")
#define TCGEN05_WAIT_LD() asm volatile("tcgen05.wait::ld.sync.aligned;" ::: "memory")
#define FENCE_PROXY_ASYNC() asm volatile("fence.proxy.async.shared::cta;" ::: "memory")

#define LDTM_X32(r, a) \
    asm volatile("tcgen05.ld.sync.aligned.32x32b.x32.b32 "                     \
        "{%0,%1,%2,%3,%4,%5,%6,%7,%8,%9,%10,%11,%12,%13,%14,%15,"              \
        "%16,%17,%18,%19,%20,%21,%22,%23,%24,%25,%26,%27,%28,%29,%30,%31}, [%32];" \
        : "=r"((r)[0]), "=r"((r)[1]), "=r"((r)[2]), "=r"((r)[3]),              \
          "=r"((r)[4]), "=r"((r)[5]), "=r"((r)[6]), "=r"((r)[7]),              \
          "=r"((r)[8]), "=r"((r)[9]), "=r"((r)[10]), "=r"((r)[11]),            \
          "=r"((r)[12]), "=r"((r)[13]), "=r"((r)[14]), "=r"((r)[15]),          \
          "=r"((r)[16]), "=r"((r)[17]), "=r"((r)[18]), "=r"((r)[19]),          \
          "=r"((r)[20]), "=r"((r)[21]), "=r"((r)[22]), "=r"((r)[23]),          \
          "=r"((r)[24]), "=r"((r)[25]), "=r"((r)[26]), "=r"((r)[27]),          \
          "=r"((r)[28]), "=r"((r)[29]), "=r"((r)[30]), "=r"((r)[31])           \
        : "r"(a))

__device__ __forceinline__ void mma_tf32_ss(uint32_t d, uint64_t ad, uint64_t bd,
                                            uint32_t idesc, uint32_t en) {
    asm volatile(
        "{\n\t.reg .pred p;\n\tsetp.ne.u32 p, %5, 0;\n\t"
        "tcgen05.mma.cta_group::1.kind::tf32 [%0], %1, %2, %3, {%4,%4,%4,%4}, p;\n\t}"
        :: "r"(d), "l"(ad), "l"(bd), "r"(idesc), "r"(0u), "r"(en) : "memory");
}
#endif  // HAS_TCGEN05

// mbarrier layout: full[s] at sb+8+s*16, empty[s] at sb+16+s*16, done at sb+56
#define FULLB(sb, s)  ((sb) + 8 + (s) * 16)
#define EMPTYB(sb, s) ((sb) + 16 + (s) * 16)
#define DONEB(sb)     ((sb) + 8 + STAGES * 16)

__global__ void __launch_bounds__(NT, 1)
gemm_tc(const float* __restrict__ bias, float* __restrict__ Y) {
#if HAS_TCGEN05
    extern __shared__ char smem[];
    const uint32_t sb = smem_u32(smem);
    const int tid = threadIdx.x;
    const int wid = tid >> 5;
    const int lane = tid & 31;
    const int m0 = blockIdx.y * BM;
    const int n0 = blockIdx.x * BN;

    if (wid == 8) TCGEN05_ALLOC(sb, 512);
    if (tid == 0) {
#pragma unroll
        for (int s = 0; s < STAGES; s++) {
            MBARRIER_INIT(FULLB(sb, s), 256);   // one arrive per producer thread
            MBARRIER_INIT(EMPTYB(sb, s), 1);    // tcgen05.commit arrives one
        }
        MBARRIER_INIT(DONEB(sb), 1);
    }
    __syncthreads();
    uint32_t tmem;
    asm volatile("ld.shared.b32 %0, [%1];" : "=r"(tmem) : "r"(sb));

    if (wid < 8) {
        // ---------------- producers: warps 0-7 (256 threads) ----------------
        const int row8 = tid >> 3;        // 0..31 -> covers 256 rows over 8 iters
        const int c    = tid & 7;         // 16B chunk within 128B row
        const float* Xp = g_X + (size_t)m0 * IN_F;
        const float* Wp = g_W + (size_t)n0 * IN_F;
        for (int kt = 0; kt < NKI; kt++) {
            const int b = kt % STAGES;
            if (kt >= STAGES)
                MBARRIER_WAIT_PARITY(EMPTYB(sb, b), (uint32_t)((kt / STAGES + 1) & 1));
            const uint32_t abase = sb + SMEM_STAGE0 + b * STAGE_BYTES;
            const uint32_t bbase = abase + 32768;
            const size_t ko = (size_t)kt * KC;
#pragma unroll
            for (int i = 0; i < 8; i++) {
                const int row = i * 32 + row8;
                const uint32_t sw = (uint32_t)(row * 128 + ((c ^ (row & 7)) << 4));
                CP_ASYNC16(abase + sw,
                           __cvta_generic_to_global(Xp + (size_t)row * IN_F + ko + c * 4));
            }
#pragma unroll
            for (int i = 0; i < 8; i++) {
                const int row = i * 32 + row8;
                const uint32_t sw = (uint32_t)(row * 128 + ((c ^ (row & 7)) << 4));
                CP_ASYNC16(bbase + sw,
                           __cvta_generic_to_global(Wp + (size_t)row * IN_F + ko + c * 4));
            }
            CP_ASYNC_MBAR_ARRIVE(FULLB(sb, b));
        }
    } else if (tid == 256) {
        // ---------------- MMA issuer: one thread of warp 8 ----------------
        for (int kt = 0; kt < NKI; kt++) {
            const int b = kt % STAGES;
            MBARRIER_WAIT_PARITY(FULLB(sb, b), (uint32_t)((kt / STAGES) & 1));
            FENCE_PROXY_ASYNC();
            const uint32_t ss = sb + SMEM_STAGE0 + b * STAGE_BYTES;
            const uint64_t a0 = MAKE_DESC(ss);
            const uint64_t a1 = MAKE_DESC(ss + 16384);   // A rows 128-255
            const uint64_t bd = MAKE_DESC(ss + 32768);
#pragma unroll
            for (int ks = 0; ks < 4; ks++) {             // 4 x K=8 within 128B row
                const uint32_t en = (kt > 0 || ks > 0) ? 1u : 0u;
                mma_tf32_ss(tmem,       a0 + ks * 2, bd + ks * 2, MMA_IDESC, en);
                mma_tf32_ss(tmem + 256, a1 + ks * 2, bd + ks * 2, MMA_IDESC, en);
            }
            TCGEN05_COMMIT(EMPTYB(sb, b));               // frees buffer b for producers
        }
        TCGEN05_COMMIT(DONEB(sb));                       // in-order: fires when ALL MMAs done
    }

    // ---------------- epilogue: warps 8-11 ----------------
    if (wid >= 8) {
        MBARRIER_WAIT_PARITY(DONEB(sb), 0u);
        TCGEN05_FENCE_AFTER();
        const int wid2 = wid - 8;
#pragma unroll
        for (int half = 0; half < 2; half++) {
            const int m = m0 + half * 128 + wid2 * 32 + lane;
            float* yrow = Y + (size_t)m * OUT_F + n0;
#pragma unroll
            for (int c0 = 0; c0 < 256; c0 += 32) {
                uint32_t r[32];
                LDTM_X32(r, tmem + half * 256 + c0);
                TCGEN05_WAIT_LD();
                const float* bp = bias + n0 + c0;
#pragma unroll
                for (int j = 0; j < 32; j += 4) {
                    float4 v;
                    v.x = __uint_as_float(r[j + 0]) + bp[j + 0];
                    v.y = __uint_as_float(r[j + 1]) + bp[j + 1];
                    v.z = __uint_as_float(r[j + 2]) + bp[j + 2];
                    v.w = __uint_as_float(r[j + 3]) + bp[j + 3];
                    *reinterpret_cast<float4*>(yrow + c0 + j) = v;
                }
            }
        }
        TCGEN05_FENCE_BEFORE();
    }

    __syncthreads();
    if (tid == 0) {
#pragma unroll
        for (int s = 0; s < STAGES; s++) {
            MBARRIER_INVAL(FULLB(sb, s));
            MBARRIER_INVAL(EMPTYB(sb, s));
        }
        MBARRIER_INVAL(DONEB(sb));
    }
    __syncthreads();
    if (wid == 8) {
        TCGEN05_RELINQUISH();
        TCGEN05_DEALLOC(tmem, 512);
    }
#endif  // HAS_TCGEN05
}

// ---------------------------------------------------------------- launch
extern "C" void kernel_launch(void* const* d_in, const int* in_sizes, int n_in,
                              void* d_out, int out_size) {
    const float* x       = (const float*)d_in[0];
    const int*   packed  = (const int*)d_in[1];
    const float* scales  = (const float*)d_in[2];
    const float* offsets = (const float*)d_in[3];
    const float* bias    = (const float*)d_in[4];
    float* out = (float*)d_out;

    // fused prepass: X tf32-round (32768 blocks) + W dequant (32768 blocks)
    prepass_kernel<<<65536, 256>>>(x, packed, scales, offsets);

    // main GEMM: 256x256 CTA tiles, tcgen05 tf32, warp-specialized pipeline
    static bool attr_set = false;
    if (!attr_set) {
        cudaFuncSetAttribute(gemm_tc, cudaFuncAttributeMaxDynamicSharedMemorySize, SMEM_TOTAL);
        attr_set = true;
    }
    dim3 grid(OUT_F / BN, M_TOT / BM);   // (16, 32)
    gemm_tc<<<grid, NT, SMEM_TOTAL>>>(bias, out);
}